// round 17
// baseline (speedup 1.0000x reference)
#include <cuda_runtime.h>
#include <math.h>

// Problem constants (fixed by the reference)
#define S_SZ  4096
#define D_SZ  300
#define C_SZ  4
#define D4    75            // float4 per embedding row
#define NB    128           // blocks (fully resident)
#define RPB   32            // sequence rows per block
#define NT    512           // threads per block (16 warps)

// Scratch (device globals; no allocation allowed)
__device__ float    g_part1[D_SZ * NB];   // transposed [d][b]
__device__ float    g_t[D_SZ];
__device__ float    g_w2mid[C_SZ];
__device__ float    g_psum[NB];           // per-block unnormalized exp sums
__device__ float    g_y[C_SZ * NB];       // per-block W2 . (unnorm weighted sum)
__device__ float    g_sink;
__device__ unsigned g_cnt[3];             // grid barrier counts (self-reset)
__device__ unsigned g_gen[3];             // grid barrier gens (monotonic)

__device__ __forceinline__ float warp_sum(float p) {
    #pragma unroll
    for (int o = 16; o > 0; o >>= 1) p += __shfl_xor_sync(0xFFFFFFFFu, p, o);
    return p;
}

// Flat grid barrier (R7-proven, best variant found). acq_rel arrival; bare
// ld.acquire spin. Count self-resets; gen monotonic -> graph-replay safe.
__device__ __forceinline__ void gbar(int i) {
    __syncthreads();
    if (threadIdx.x == 0) {
        unsigned g;
        asm volatile("ld.relaxed.gpu.u32 %0,[%1];"
                     : "=r"(g) : "l"(&g_gen[i]) : "memory");
        unsigned old;
        asm volatile("atom.acq_rel.gpu.add.u32 %0,[%1],%2;"
                     : "=r"(old) : "l"(&g_cnt[i]), "r"(1u) : "memory");
        if (old == NB - 1) {
            asm volatile("st.relaxed.gpu.u32 [%0],%1;"
                         :: "l"(&g_cnt[i]), "r"(0u) : "memory");
            unsigned d;
            asm volatile("atom.acq_rel.gpu.add.u32 %0,[%1],%2;"
                         : "=r"(d) : "l"(&g_gen[i]), "r"(1u) : "memory");
        } else {
            unsigned cur;
            do {
                asm volatile("ld.acquire.gpu.u32 %0,[%1];"
                             : "=r"(cur) : "l"(&g_gen[i]) : "memory");
            } while (cur == g);
        }
    }
    __syncthreads();
}

__device__ __forceinline__ float dot4(float4 a, float4 b) {
    return fmaf(a.x, b.x, fmaf(a.y, b.y, fmaf(a.z, b.z, a.w * b.w)));
}

// Warp dot of a preloaded 300-float row (3 float4/lane) with an smem vector.
__device__ __forceinline__ float warp_dot_pre(float4 a0, float4 a1, float4 a2,
                                              const float4* __restrict__ v4,
                                              int lane) {
    float p = dot4(a0, v4[lane]) + dot4(a1, v4[lane + 32]);
    if (lane < D4 - 64) p += dot4(a2, v4[lane + 64]);
    return warp_sum(p);
}

// Warp dot of a global 300-float row (L2-warm) with an smem vector.
__device__ __forceinline__ float warp_dot_gl(const float4* __restrict__ row,
                                             const float4* __restrict__ v4,
                                             int lane) {
    float4 a0 = __ldg(&row[lane]);
    float4 a1 = __ldg(&row[lane + 32]);
    float p = dot4(a0, v4[lane]) + dot4(a1, v4[lane + 32]);
    if (lane < D4 - 64) p += dot4(__ldg(&row[lane + 64]), v4[lane + 64]);
    return warp_sum(p);
}

// ---------------------------------------------------------------------------
__global__ __launch_bounds__(NT)
void fused(const int* __restrict__ x, const float* __restrict__ emb,
           const float* __restrict__ W1, const float* __restrict__ b1,
           const float* __restrict__ Wb, const float* __restrict__ bb,
           const float* __restrict__ W2, const float* __restrict__ b2,
           float* __restrict__ out)
{
    const int b = blockIdx.x, tid = threadIdx.x;
    const int lane = tid & 31, w = tid >> 5;

    __shared__ float4 s_emb[RPB][D4];   // staged embedding rows (38.4 KB)
    __shared__ float4 s_acc[4][D4];
    __shared__ float4 s_v4[D4 + 1];     // dense -> t vector
    __shared__ float4 s_m4[D4 + 1];     // mid (block 0 chain only)
    __shared__ float  s_sc[RPB];
    __shared__ float  s_e[RPB];
    __shared__ float  s_bc;
    __shared__ int    s_idx[RPB];
    float* s_v = (float*)s_v4;
    float* s_m = (float*)s_m4;

    if (tid < RPB) s_idx[tid] = __ldg(&x[b * RPB + tid]);
    __syncthreads();

    // ---- Register preloads: W2 rows only (warps 4-7; used for y and w2mid)
    const float4 z = make_float4(0.f, 0.f, 0.f, 0.f);
    float4 wC0 = z, wC1 = z, wC2 = z;
    if (w >= 4 && w < 4 + C_SZ) {
        const float4* wr2 = (const float4*)(W2 + (long)(w - 4) * D_SZ);
        wC0 = __ldg(&wr2[lane]);  wC1 = __ldg(&wr2[lane + 32]);
        if (lane < D4 - 64) wC2 = __ldg(&wr2[lane + 64]);
    }

    const float4* emb4 = (const float4*)emb;

    // ---- Phase A: gather 32 rows (DRAM) -> smem stage + per-block partials;
    //      idle threads (300..511) prefetch W1/Wb into L2 for the chain.
    if (tid < D_SZ) {
        const int c = tid % D4, g = tid / D4;
        float4 acc = z;
        #pragma unroll
        for (int k = 0; k < 8; k++) {
            const int r = g * 8 + k;
            float4 v = __ldg(&emb4[(long)s_idx[r] * D4 + c]);
            s_emb[r][c] = v;
            acc.x += v.x; acc.y += v.y; acc.z += v.z; acc.w += v.w;
        }
        s_acc[g][c] = acc;
    } else {
        const long i = (long)b * 212 + (tid - D_SZ);   // covers 22500 float4
        if (i < 22500) {
            float4 a = __ldg(&((const float4*)W1)[i]);
            float4 c = __ldg(&((const float4*)Wb)[i]);
            float s = a.x + c.w;
            if (s != s) g_sink = s;                    // keep loads; never fires
        }
    }
    __syncthreads();
    if (tid < D4) {
        float4 t0 = s_acc[0][tid], t1 = s_acc[1][tid];
        float4 t2 = s_acc[2][tid], t3 = s_acc[3][tid];
        g_part1[(4 * tid + 0) * NB + b] = (t0.x + t1.x) + (t2.x + t3.x);
        g_part1[(4 * tid + 1) * NB + b] = (t0.y + t1.y) + (t2.y + t3.y);
        g_part1[(4 * tid + 2) * NB + b] = (t0.z + t1.z) + (t2.z + t3.z);
        g_part1[(4 * tid + 3) * NB + b] = (t0.w + t1.w) + (t2.w + t3.w);
    }
    gbar(0);

    // ---- Chain (block 0 only): dense -> mid -> t + W2*mid, all in-block.
    // Other 127 blocks go straight to the bar1 spin. W1/Wb are L2-warm.
    if (b == 0) {
        // dense: warp-per-d, coalesced, same reduction order as before
        for (int d = w; d < D_SZ; d += 16) {
            const float* pp = g_part1 + (long)d * NB;
            float v = (pp[lane] + pp[lane + 32]) + (pp[lane + 64] + pp[lane + 96]);
            v = warp_sum(v);
            if (lane == 0) s_v[d] = v * (1.0f / S_SZ);
        }
        __syncthreads();
        // mid = W1*dense + b1 (warp-per-row, rows w, w+16, ...)
        for (int r = w; r < D_SZ; r += 16) {
            float p = warp_dot_gl((const float4*)(W1 + (long)r * D_SZ), s_v4, lane);
            if (lane == 0) s_m[r] = p + __ldg(&b1[r]);
        }
        __syncthreads();
        // t = Wb*mid (warp-per-row); warps 4-7 then add w2mid from registers
        for (int r = w; r < D_SZ; r += 16) {
            float p = warp_dot_gl((const float4*)(Wb + (long)r * D_SZ), s_m4, lane);
            if (lane == 0) g_t[r] = p;
        }
        if (w >= 4 && w < 4 + C_SZ) {
            float p = warp_dot_pre(wC0, wC1, wC2, s_m4, lane);
            if (lane == 0) g_w2mid[w - 4] = p;
        }
    }
    gbar(1);

    // ---- Phase E: scores/exp/psum + unnormalized weighted sum + y, all smem
    for (int d = tid; d < D_SZ; d += NT) s_v[d] = g_t[d];
    __syncthreads();
    {
        const float bias = __ldg(bb);
        #pragma unroll
        for (int j = 0; j < 2; j++) {
            const int r = w * 2 + j;
            float p = dot4(s_emb[r][lane], s_v4[lane])
                    + dot4(s_emb[r][lane + 32], s_v4[lane + 32]);
            if (lane < D4 - 64) p += dot4(s_emb[r][lane + 64], s_v4[lane + 64]);
            p = warp_sum(p);
            if (lane == 0) s_sc[r] = p + bias;
        }
    }
    __syncthreads();
    if (w == 0) {                   // scores tiny -> unshifted exp exact-safe
        float e = expf(s_sc[lane]);
        s_e[lane] = e;
        float ps = warp_sum(e);
        if (lane == 0) g_psum[b] = ps;
    }
    __syncthreads();
    if (tid < D_SZ) {               // weighted sum with raw e (pure smem)
        const int c = tid % D4, g = tid / D4;
        float4 acc = z;
        #pragma unroll
        for (int k = 0; k < 8; k++) {
            const int r = g * 8 + k;
            const float wt = s_e[r];
            float4 v = s_emb[r][c];
            acc.x = fmaf(wt, v.x, acc.x); acc.y = fmaf(wt, v.y, acc.y);
            acc.z = fmaf(wt, v.z, acc.z); acc.w = fmaf(wt, v.w, acc.w);
        }
        s_acc[g][c] = acc;
    }
    __syncthreads();
    if (tid < D4) {                 // t consumed: reuse s_v4 for the partial
        float4 t0 = s_acc[0][tid], t1 = s_acc[1][tid];
        float4 t2 = s_acc[2][tid], t3 = s_acc[3][tid];
        s_v4[tid] = make_float4((t0.x + t1.x) + (t2.x + t3.x),
                                (t0.y + t1.y) + (t2.y + t3.y),
                                (t0.z + t1.z) + (t2.z + t3.z),
                                (t0.w + t1.w) + (t2.w + t3.w));
    }
    __syncthreads();
    if (w >= 4 && w < 4 + C_SZ) {   // y_b[c] = W2[c,:] . block_partial
        float p = warp_dot_pre(wC0, wC1, wC2, s_v4, lane);
        if (lane == 0) g_y[(w - 4) * NB + b] = p;
    }
    gbar(2);

    // ---- Phase F: redundant total (identical order), rewards, logits
    if (w == 0) {
        float v = (g_psum[lane] + g_psum[lane + 32])
                + (g_psum[lane + 64] + g_psum[lane + 96]);
        v = warp_sum(v);
        if (lane == 0) s_bc = 1.0f / v;
    }
    __syncthreads();
    const float inv = s_bc;
    if (tid < RPB)
        out[C_SZ + b * RPB + tid] = s_e[tid] * inv;

    if (b == 0 && w < C_SZ) {
        const float* yy = g_y + (long)w * NB;
        float v = (yy[lane] + yy[lane + 32]) + (yy[lane + 64] + yy[lane + 96]);
        v = warp_sum(v);
        if (lane == 0)
            out[w] = g_w2mid[w] + v * inv * (1.0f / S_SZ) + __ldg(&b2[w]);
    }
}

// ---------------------------------------------------------------------------
extern "C" void kernel_launch(void* const* d_in, const int* in_sizes, int n_in,
                              void* d_out, int out_size)
{
    const int*   x   = (const int*)  d_in[0];
    const float* emb = (const float*)d_in[1];
    const float* W1  = (const float*)d_in[2];
    const float* b1  = (const float*)d_in[3];
    const float* Wb  = (const float*)d_in[4];
    const float* bb  = (const float*)d_in[5];
    const float* W2  = (const float*)d_in[6];
    const float* b2  = (const float*)d_in[7];
    float* out = (float*)d_out;   // out[0:4] = output, out[4:4100] = reward

    fused<<<NB, NT>>>(x, emb, W1, b1, Wb, bb, W2, b2, out);
}